// round 6
// baseline (speedup 1.0000x reference)
#include <cuda_runtime.h>
#include <cuda_bf16.h>

typedef unsigned long long u64;

constexpr int B = 4096, T = 200, F = 36;
constexpr int THREADS = 256;
constexpr int BPB  = 32;
constexpr int GRID = B / BPB;     // 128

// shared memory layout (u64 units; all values stored duplicated {v,v})
constexpr int XBUF_OFF = 0;                       // [2][32][36]
constexpr int H1_OFF   = XBUF_OFF + 2 * 32 * 36;  // [2][32][16]
constexpr int H2_OFF   = H1_OFF + 2 * 32 * 16;    // [2][32][32]
constexpr int H3_OFF   = H2_OFF + 2 * 32 * 32;    // [32][16]
constexpr int XCH_OFF  = H3_OFF + 32 * 16;        // [4][8][32]
constexpr int SMEM_U64 = XCH_OFF + 4 * 8 * 32;
constexpr int SMEM_BYTES = SMEM_U64 * 8;          // 55296

__device__ float g_Wc[6 * 16];
__device__ float g_bc[6];

__device__ __forceinline__ void fma2(u64 &acc, u64 w, u64 x) {
    asm("fma.rn.f32x2 %0, %1, %2, %0;" : "+l"(acc) : "l"(w), "l"(x));
}
__device__ __forceinline__ u64 pk(float v) {
    u64 r; asm("mov.b64 %0, {%1, %1};" : "=l"(r) : "f"(v)); return r;
}
__device__ __forceinline__ u64 pkp(float lo, float hi) {
    u64 r; asm("mov.b64 %0, {%1, %2};" : "=l"(r) : "f"(lo), "f"(hi)); return r;
}
__device__ __forceinline__ void upk(u64 v, float &lo, float &hi) {
    asm("mov.b64 {%0, %1}, %2;" : "=f"(lo), "=f"(hi) : "l"(v));
}
__device__ __forceinline__ float sigf(float x) {
    return __fdividef(1.0f, 1.0f + __expf(-x));
}
__device__ __forceinline__ float tanh_(float x) {
    return __fdividef(2.0f, 1.0f + __expf(-2.0f * x)) - 1.0f;
}
// gates: ifp={pre_i,pre_f}, gop={pre_g,pre_o}; updates c, returns h
__device__ __forceinline__ float gate_h(u64 ifp, u64 gop, float &c) {
    float pi, pf, pg, po;
    upk(ifp, pi, pf);
    upk(gop, pg, po);
    float cc = fmaf(sigf(pf), c, sigf(pi) * tanh_(pg));
    c = cc;
    return sigf(po) * tanh_(cc);
}
// load weight row-pair (rA,rB) of W[rows][C] into dst as {wA,wB} u64 per col
template<int C>
__device__ __forceinline__ void load_wpair(u64* dst, const float* W, int rA, int rB) {
    #pragma unroll
    for (int j4 = 0; j4 < C / 4; j4++) {
        float4 a = __ldg(reinterpret_cast<const float4*>(W + (size_t)rA * C) + j4);
        float4 b = __ldg(reinterpret_cast<const float4*>(W + (size_t)rB * C) + j4);
        dst[j4 * 4 + 0] = pkp(a.x, b.x);
        dst[j4 * 4 + 1] = pkp(a.y, b.y);
        dst[j4 * 4 + 2] = pkp(a.z, b.z);
        dst[j4 * 4 + 3] = pkp(a.w, b.w);
    }
}

struct XStage { float4 v[5]; };

__device__ __forceinline__ void x_ldg(XStage &s, const float* x, int gb0, int t, int lane) {
    #pragma unroll
    for (int r = 0; r < 5; r++) {
        int f = lane + 32 * r;
        if (f < 144) {
            int b = f / 9, q = f - 9 * b;
            s.v[r] = __ldg(reinterpret_cast<const float4*>(
                x + ((size_t)(gb0 + b) * T + t) * F) + q);
        }
    }
}
__device__ __forceinline__ void x_sts(const XStage &s, u64* XB, int lane) {
    #pragma unroll
    for (int r = 0; r < 5; r++) {
        int f = lane + 32 * r;
        if (f < 144) {
            int b = f / 9, q = f - 9 * b;
            u64* dst = XB + b * 36 + q * 4;
            *reinterpret_cast<ulonglong2*>(dst)     = make_ulonglong2(pk(s.v[r].x), pk(s.v[r].y));
            *reinterpret_cast<ulonglong2*>(dst + 2) = make_ulonglong2(pk(s.v[r].z), pk(s.v[r].w));
        }
    }
}

__global__ void __launch_bounds__(THREADS, 1) lstm_fused(
    const float* __restrict__ x,
    const float* __restrict__ Wih1, const float* __restrict__ Whh1,
    const float* __restrict__ bih1, const float* __restrict__ bhh1,
    const float* __restrict__ Wih2, const float* __restrict__ Whh2,
    const float* __restrict__ bih2, const float* __restrict__ bhh2,
    const float* __restrict__ Wih3, const float* __restrict__ Whh3,
    const float* __restrict__ bih3, const float* __restrict__ bhh3,
    float* __restrict__ out)
{
    extern __shared__ u64 smu[];
    u64* XBUF = smu + XBUF_OFF;
    u64* H1   = smu + H1_OFF;
    u64* H2   = smu + H2_OFF;
    u64* H3   = smu + H3_OFF;
    u64* XCH  = smu + XCH_OFF;

    const int tid  = threadIdx.x;
    const int lane = tid & 31;
    const int wid  = tid >> 5;
    const int blk_b0 = blockIdx.x * BPB;

    // zero h buffers
    for (int idx = tid; idx < 2 * 32 * 16 + 2 * 32 * 32 + 32 * 16; idx += THREADS)
        H1[idx] = 0ull;

    // per-role persistent registers
    u64 wx[36], wh[32], bias;
    u64 acc[16];
    float cst[8];
    #pragma unroll
    for (int b = 0; b < 8; b++) cst[b] = 0.0f;
    XStage xs;

    // ---- weight prologue (registers, loaded once) ----
    if (wid < 2) {                       // L1: 64 rows, in 36, rec 16
        int u = lane & 15;
        int rA = (lane < 16) ? u : 32 + u;    // i | g
        int rB = (lane < 16) ? 16 + u : 48 + u;  // f | o
        load_wpair<36>(wx, Wih1, rA, rB);
        load_wpair<16>(wh, Whh1, rA, rB);
        bias = pkp(bih1[rA] + bhh1[rA], bih1[rB] + bhh1[rB]);
        // stage x[0]
        x_ldg(xs, x, blk_b0 + wid * 16, 0, lane);
        x_sts(xs, XBUF + 0 * (32 * 36) + wid * 16 * 36, lane);
    } else if (wid < 6) {                // L2: 128 rows, in 16, rec 32
        int isIF = ((wid - 2) & 1) == 0;
        int u = lane;
        int rA = isIF ? u : 64 + u;          // i | g
        int rB = isIF ? 32 + u : 96 + u;     // f | o
        load_wpair<16>(wx, Wih2, rA, rB);
        load_wpair<32>(wh, Whh2, rA, rB);
        bias = pkp(bih2[rA] + bhh2[rA], bih2[rB] + bhh2[rB]);
    } else {                             // L3: 64 rows, in 32, rec 16
        int u = lane & 15;
        int rA = (lane < 16) ? u : 32 + u;
        int rB = (lane < 16) ? 16 + u : 48 + u;
        load_wpair<32>(wx, Wih3, rA, rB);
        load_wpair<16>(wh, Whh3, rA, rB);
        bias = pkp(bih3[rA] + bhh3[rA], bih3[rB] + bhh3[rB]);
    }
    __syncthreads();

    #pragma unroll 1
    for (int i = 0; i <= T + 1; i++) {
        // ================= phase A =================
        if (wid < 2) {
            // prefetch x[i+1] early so LDG latency hides under this phase
            if (i < T - 1)
                x_ldg(xs, x, blk_b0 + wid * 16, i + 1, lane);
            if (i < T) {
                #pragma unroll
                for (int b = 0; b < 16; b++) acc[b] = bias;
                const u64* xb = XBUF + (i & 1) * (32 * 36) + wid * 16 * 36;
                #pragma unroll
                for (int j = 0; j < 36; j += 2) {
                    #pragma unroll
                    for (int b = 0; b < 16; b++) {
                        ulonglong2 xv = *reinterpret_cast<const ulonglong2*>(xb + b * 36 + j);
                        fma2(acc[b], wx[j], xv.x);
                        fma2(acc[b], wx[j + 1], xv.y);
                    }
                }
                const u64* hb = H1 + ((i + 1) & 1) * (32 * 16) + wid * 16 * 16;
                #pragma unroll
                for (int j = 0; j < 16; j += 2) {
                    #pragma unroll
                    for (int b = 0; b < 16; b++) {
                        ulonglong2 hv = *reinterpret_cast<const ulonglong2*>(hb + b * 16 + j);
                        fma2(acc[b], wh[j], hv.x);
                        fma2(acc[b], wh[j + 1], hv.y);
                    }
                }
                __syncwarp();
                u64 part[8];
                #pragma unroll
                for (int b = 0; b < 8; b++) {
                    u64 sendv = (lane < 16) ? acc[b + 8] : acc[b];
                    part[b] = __shfl_xor_sync(0xffffffffu, sendv, 16);
                }
                u64* hdst = H1 + (i & 1) * (32 * 16) + wid * 16 * 16;
                int u = lane & 15;
                #pragma unroll
                for (int b = 0; b < 8; b++) {
                    u64 ifp = (lane < 16) ? acc[b] : part[b];
                    u64 gop = (lane < 16) ? part[b] : acc[b + 8];
                    int batch = (lane < 16) ? b : b + 8;
                    float h = gate_h(ifp, gop, cst[b]);
                    hdst[batch * 16 + u] = pk(h);
                }
            }
        } else if (wid < 6) {
            if (i >= 1 && i <= T) {
                int pair = (wid - 2) >> 1;
                int isIF = ((wid - 2) & 1) == 0;
                #pragma unroll
                for (int b = 0; b < 16; b++) acc[b] = bias;
                const u64* h1s = H1 + ((i + 1) & 1) * (32 * 16) + pair * 16 * 16;
                #pragma unroll
                for (int j = 0; j < 16; j += 2) {
                    #pragma unroll
                    for (int b = 0; b < 16; b++) {
                        ulonglong2 hv = *reinterpret_cast<const ulonglong2*>(h1s + b * 16 + j);
                        fma2(acc[b], wx[j], hv.x);
                        fma2(acc[b], wx[j + 1], hv.y);
                    }
                }
                const u64* h2s = H2 + (i & 1) * (32 * 32) + pair * 16 * 32;
                #pragma unroll
                for (int j = 0; j < 32; j += 2) {
                    #pragma unroll
                    for (int b = 0; b < 16; b++) {
                        ulonglong2 hv = *reinterpret_cast<const ulonglong2*>(h2s + b * 32 + j);
                        fma2(acc[b], wh[j], hv.x);
                        fma2(acc[b], wh[j + 1], hv.y);
                    }
                }
                // publish preacts for partner warp's batch half
                u64* xm = XCH + (pair * 2 + (isIF ? 0 : 1)) * (8 * 32);
                #pragma unroll
                for (int b = 0; b < 8; b++)
                    xm[b * 32 + lane] = acc[isIF ? (b + 8) : b];
            }
        } else {
            if (i >= 2) {
                int wb = wid - 6;
                #pragma unroll
                for (int b = 0; b < 16; b++) acc[b] = bias;
                const u64* h2s = H2 + (i & 1) * (32 * 32) + wb * 16 * 32;
                #pragma unroll
                for (int j = 0; j < 32; j += 2) {
                    #pragma unroll
                    for (int b = 0; b < 16; b++) {
                        ulonglong2 hv = *reinterpret_cast<const ulonglong2*>(h2s + b * 32 + j);
                        fma2(acc[b], wx[j], hv.x);
                        fma2(acc[b], wx[j + 1], hv.y);
                    }
                }
                const u64* h3s = H3 + wb * 16 * 16;
                #pragma unroll
                for (int j = 0; j < 16; j += 2) {
                    #pragma unroll
                    for (int b = 0; b < 16; b++) {
                        ulonglong2 hv = *reinterpret_cast<const ulonglong2*>(h3s + b * 16 + j);
                        fma2(acc[b], wh[j], hv.x);
                        fma2(acc[b], wh[j + 1], hv.y);
                    }
                }
                __syncwarp();
                u64 part[8];
                #pragma unroll
                for (int b = 0; b < 8; b++) {
                    u64 sendv = (lane < 16) ? acc[b + 8] : acc[b];
                    part[b] = __shfl_xor_sync(0xffffffffu, sendv, 16);
                }
                u64* hdst = H3 + wb * 16 * 16;
                int u = lane & 15;
                #pragma unroll
                for (int b = 0; b < 8; b++) {
                    u64 ifp = (lane < 16) ? acc[b] : part[b];
                    u64 gop = (lane < 16) ? part[b] : acc[b + 8];
                    int batch = (lane < 16) ? b : b + 8;
                    float h = gate_h(ifp, gop, cst[b]);
                    hdst[batch * 16 + u] = pk(h);
                }
            }
        }
        __syncthreads();

        // ================= phase B =================
        if (wid < 2) {
            if (i < T - 1)
                x_sts(xs, XBUF + ((i + 1) & 1) * (32 * 36) + wid * 16 * 36, lane);
        } else if (wid < 6) {
            if (i >= 1 && i <= T) {
                int pair = (wid - 2) >> 1;
                int isIF = ((wid - 2) & 1) == 0;
                const u64* xp = XCH + (pair * 2 + (isIF ? 1 : 0)) * (8 * 32);
                u64* hdst = H2 + ((i + 1) & 1) * (32 * 32) + pair * 16 * 32;
                #pragma unroll
                for (int b = 0; b < 8; b++) {
                    u64 pv = xp[b * 32 + lane];
                    u64 ifp = isIF ? acc[b] : pv;
                    u64 gop = isIF ? pv : acc[b + 8];
                    int batch = isIF ? b : b + 8;
                    float h = gate_h(ifp, gop, cst[b]);
                    hdst[batch * 32 + lane] = pk(h);
                }
            }
        }
        __syncthreads();
    }

    // ---- collapsed head: out = h3_final @ Wc^T + bc ----
    if (tid < 192) {
        int b = tid / 6, cls = tid - b * 6;
        const float* hrow = reinterpret_cast<const float*>(H3 + b * 16);
        float acc0 = g_bc[cls];
        #pragma unroll
        for (int u = 0; u < 16; u++)
            acc0 = fmaf(hrow[2 * u], g_Wc[cls * 16 + u], acc0);
        out[(size_t)(blk_b0 + b) * 6 + cls] = acc0;
    }
}

// Collapse the 3 linear head layers into Wc [6,16], bc [6].
__global__ void head_precompute(
    const float* __restrict__ Wfc1, const float* __restrict__ bfc1,
    const float* __restrict__ Wfc2, const float* __restrict__ bfc2,
    const float* __restrict__ Wcls, const float* __restrict__ bcls)
{
    __shared__ float tmp[6 * 128];
    const int tid = threadIdx.x;

    for (int idx = tid; idx < 6 * 128; idx += blockDim.x) {
        int j = idx / 128, p = idx % 128;
        float s = 0.0f;
        for (int q = 0; q < 32; q++)
            s += Wcls[j * 32 + q] * Wfc2[q * 128 + p];
        tmp[idx] = s;
    }
    __syncthreads();

    for (int idx = tid; idx < 6 * 16; idx += blockDim.x) {
        int j = idx / 16, u = idx % 16;
        float s = 0.0f;
        for (int p = 0; p < 128; p++)
            s += tmp[j * 128 + p] * Wfc1[p * 16 + u];
        g_Wc[idx] = s;
    }
    if (tid < 6) {
        float s = bcls[tid];
        for (int q = 0; q < 32; q++)
            s += Wcls[tid * 32 + q] * bfc2[q];
        for (int p = 0; p < 128; p++)
            s += tmp[tid * 128 + p] * bfc1[p];
        g_bc[tid] = s;
    }
}

extern "C" void kernel_launch(void* const* d_in, const int* in_sizes, int n_in,
                              void* d_out, int out_size)
{
    (void)in_sizes; (void)n_in; (void)out_size;
    const float* x    = (const float*)d_in[0];
    const float* Wih1 = (const float*)d_in[1];
    const float* Whh1 = (const float*)d_in[2];
    const float* bih1 = (const float*)d_in[3];
    const float* bhh1 = (const float*)d_in[4];
    const float* Wih2 = (const float*)d_in[5];
    const float* Whh2 = (const float*)d_in[6];
    const float* bih2 = (const float*)d_in[7];
    const float* bhh2 = (const float*)d_in[8];
    const float* Wih3 = (const float*)d_in[9];
    const float* Whh3 = (const float*)d_in[10];
    const float* bih3 = (const float*)d_in[11];
    const float* bhh3 = (const float*)d_in[12];
    const float* Wfc1 = (const float*)d_in[13];
    const float* bfc1 = (const float*)d_in[14];
    const float* Wfc2 = (const float*)d_in[15];
    const float* bfc2 = (const float*)d_in[16];
    const float* Wcls = (const float*)d_in[17];
    const float* bcls = (const float*)d_in[18];
    float* out = (float*)d_out;

    static bool attr_set = false;
    if (!attr_set) {
        cudaFuncSetAttribute(lstm_fused,
                             cudaFuncAttributeMaxDynamicSharedMemorySize,
                             SMEM_BYTES);
        attr_set = true;
    }

    head_precompute<<<1, 256>>>(Wfc1, bfc1, Wfc2, bfc2, Wcls, bcls);
    lstm_fused<<<GRID, THREADS, SMEM_BYTES>>>(
        x, Wih1, Whh1, bih1, bhh1, Wih2, Whh2, bih2, bhh2,
        Wih3, Whh3, bih3, bhh3, out);
}